// round 12
// baseline (speedup 1.0000x reference)
#include <cuda_runtime.h>
#include <cuda_fp16.h>
#include <cstdint>

// ---------------------------------------------------------------------------
// Problem shape (fixed by dataset)
// ---------------------------------------------------------------------------
static constexpr int GM = 8192;          // batch
static constexpr int GN = 512;           // out_count
static constexpr int GIN = 512;          // in_count
static constexpr int NB = 8;             // num_basis
static constexpr int GK = GIN * NB;      // 4096 (reduction dim, (i,m) order)

// GEMM tiling: BM=64, BN=256, BK=64; warp-specialized CTA (192 threads):
//   warps 0-3 : consumers, 1(M) x 4(N), warp tile 64x64, MMA only
//   warps 4-5 : producers, A-tile tanh production + all B cp.async
// 2 CTAs/SM (smem 92KB/CTA), grid 256 -> all 148 SMs busy.
static constexpr int BM = 64, BN = 256, BK = 64;
static constexpr int KT = GK / BK;       // 64 k-tiles
static constexpr int LDS = BK + 8;       // 72 halves row stride (144B, conflict-free)
static constexpr int A_STAGE_BYTES = BM * LDS * 2;   //  9216 (A double-buffered)
static constexpr int B_STAGE_BYTES = BN * LDS * 2;   // 36864 (B double-buffered)

static constexpr int A_OFF = 0;                              // 2 * 9216
static constexpr int B_OFF = 2 * A_STAGE_BYTES;              // 18432
static constexpr int SMEM_BYTES = B_OFF + 2 * B_STAGE_BYTES; // 92160

static constexpr int THREADS = 192;      // 128 consumers + 64 producers

// Scratch (allowed: __device__ globals)
__device__ __half g_coefh[(size_t)GN * GK];   // 4 MB, [j][i*8+m]

// ---------------------------------------------------------------------------
// Helpers
// ---------------------------------------------------------------------------
__device__ __forceinline__ uint32_t h2_as_u32(__half2 v) {
    union { __half2 h; uint32_t u; } cvt;
    cvt.h = v;
    return cvt.u;
}

__device__ __forceinline__ uint32_t smem_u32(const void* p) {
    uint32_t a;
    asm("{ .reg .u64 t; cvta.to.shared.u64 t, %1; cvt.u32.u64 %0, t; }"
        : "=r"(a) : "l"(p));
    return a;
}

__device__ __forceinline__ void cp16(uint32_t dst, const void* src) {
    asm volatile("cp.async.cg.shared.global [%0], [%1], 16;\n" :: "r"(dst), "l"(src));
}

__device__ __forceinline__ void ldmatrix_x4(uint32_t* r, uint32_t addr) {
    asm volatile("ldmatrix.sync.aligned.m8n8.x4.shared.b16 {%0,%1,%2,%3}, [%4];"
                 : "=r"(r[0]), "=r"(r[1]), "=r"(r[2]), "=r"(r[3]) : "r"(addr));
}

__device__ __forceinline__ void mma_16816(float* d, const uint32_t* a, const uint32_t* b) {
    asm volatile(
        "mma.sync.aligned.m16n8k16.row.col.f32.f16.f16.f32 "
        "{%0,%1,%2,%3}, {%4,%5,%6,%7}, {%8,%9}, {%0,%1,%2,%3};"
        : "+f"(d[0]), "+f"(d[1]), "+f"(d[2]), "+f"(d[3])
        : "r"(a[0]), "r"(a[1]), "r"(a[2]), "r"(a[3]), "r"(b[0]), "r"(b[1]));
}

// ---------------------------------------------------------------------------
// Pass 1: coeffs fp32 -> fp16 (same [j][i*8+m] layout)
// ---------------------------------------------------------------------------
__global__ void __launch_bounds__(256) coef_convert_kernel(const float* __restrict__ c) {
    int idx = blockIdx.x * blockDim.x + threadIdx.x;   // per 4 elements
    float4 v = reinterpret_cast<const float4*>(c)[idx];
    __half2 a = __floats2half2_rn(v.x, v.y);
    __half2 b = __floats2half2_rn(v.z, v.w);
    uint2 o;
    o.x = h2_as_u32(a);
    o.y = h2_as_u32(b);
    reinterpret_cast<uint2*>(g_coefh)[idx] = o;
}

// ---------------------------------------------------------------------------
// Pass 2: warp-specialized FUSED basis + HMMA GEMM
//   out[M,N] = S[M,K] * coefh[N,K]^T
//   S[b][i*8+m] = 0.5*tanh(slope[i][m]*(x[b][i]-center[i][m])) + 0.5
// Producer schedule (2-deep x prefetch — keeps LDG latency off the
// critical path):
//   iteration kt: fetch_x(kt+2) -> alt reg buffer ; load_B(kt+1) ;
//                 produce_A(kt+1) from x fetched LAST iteration ;
//                 wait_group 0 ; __syncthreads
// ---------------------------------------------------------------------------
__global__ void __launch_bounds__(THREADS, 2)
gemm_kernel(const float* __restrict__ x,
            const float* __restrict__ centers,
            const float* __restrict__ slopes,
            float* __restrict__ out) {
    extern __shared__ char smbase[];
    const uint32_t sb32 = smem_u32(smbase);
    const uint32_t sA0 = sb32 + A_OFF;
    const uint32_t sB0 = sb32 + B_OFF;

    const int tid = threadIdx.x;
    const int wid = tid >> 5;
    const int lid = tid & 31;
    const int m0 = blockIdx.y * BM;
    const int n0 = blockIdx.x * BN;

    if (wid >= 4) {
        // =================== PRODUCER PATH (warps 4-5, 64 threads) =========
        const int ptid = tid - 128;           // 0..63
        const int i_local = ptid & 7;         // k-chunk channel 0..7
        const int rgrp = ptid >> 3;           // 0..7 -> rows rgrp*8 .. +7
        const float* xcol = x + (size_t)(m0 + rgrp * 8) * GIN;
        const __half* Bbase = g_coefh + (size_t)n0 * GK;

        // B loader: 2048 16B chunks per stage, 32 per producer thread
        auto load_B = [&](int kt) {
            uint32_t sbm = sB0 + (kt & 1) * B_STAGE_BYTES;
            int kofs = kt * BK;
#pragma unroll
            for (int j = 0; j < 32; j++) {
                int c = ptid + j * 64;
                int row = c >> 3;
                int cu = c & 7;
                uint32_t so = (uint32_t)(row * LDS + cu * 8) * 2;
                cp16(sbm + so, Bbase + (size_t)row * GK + kofs + cu * 8);
            }
            asm volatile("cp.async.commit_group;\n" ::: "memory");
        };

        auto fetch_x = [&](int kt, float* xr) {
            int i = kt * 8 + i_local;
#pragma unroll
            for (int r = 0; r < 8; r++)
                xr[r] = xcol[(size_t)r * GIN + i];
        };

        auto produce_A = [&](int kt, const float* xr) {
            int i = kt * 8 + i_local;
            float4 fa = *reinterpret_cast<const float4*>(slopes + i * 8);
            float4 fb = *reinterpret_cast<const float4*>(slopes + i * 8 + 4);
            float4 ca = *reinterpret_cast<const float4*>(centers + i * 8);
            float4 cb = *reinterpret_cast<const float4*>(centers + i * 8 + 4);
            float f0[8] = {fa.x, fa.y, fa.z, fa.w, fb.x, fb.y, fb.z, fb.w};
            float c0[8] = {ca.x, ca.y, ca.z, ca.w, cb.x, cb.y, cb.z, cb.w};
            float g0[8];
#pragma unroll
            for (int m = 0; m < 8; m++) g0[m] = -f0[m] * c0[m];

            uint4* ap = reinterpret_cast<uint4*>(smbase + A_OFF + (kt & 1) * A_STAGE_BYTES);
#pragma unroll
            for (int r = 0; r < 8; r++) {
                __half h[8];
#pragma unroll
                for (int m = 0; m < 8; m++) {
                    float t = fmaf(f0[m], xr[r], g0[m]);
                    float th;
                    asm("tanh.approx.f32 %0, %1;" : "=f"(th) : "f"(t));
                    h[m] = __float2half_rn(fmaf(0.5f, th, 0.5f));
                }
                uint4 o;
                o.x = h2_as_u32(__halves2half2(h[0], h[1]));
                o.y = h2_as_u32(__halves2half2(h[2], h[3]));
                o.z = h2_as_u32(__halves2half2(h[4], h[5]));
                o.w = h2_as_u32(__halves2half2(h[6], h[7]));
                ap[(rgrp * 8 + r) * 9 + i_local] = o;   // 9 uint4 per 72-half row
            }
        };

        // x register double-buffer: xr[p] holds x(kt) for the next produce_A
        float xr[2][8];

        // ---- prologue: A(0), B(0) ready; x(1) prefetched ----
        fetch_x(0, xr[0]);
        load_B(0);
        produce_A(0, xr[0]);
        fetch_x(1, xr[1]);
        asm volatile("cp.async.wait_group 0;\n" ::: "memory");
        __syncthreads();

        for (int kt = 0; kt < KT; kt++) {
            if (kt + 1 < KT) {
                // x(kt+1) already resident in xr[(kt+1)&1] (fetched last iter).
                // Prefetch x(kt+2) into the buffer x(kt) vacated.
                if (kt + 2 < KT) fetch_x(kt + 2, xr[kt & 1]);
                load_B(kt + 1);
                produce_A(kt + 1, xr[(kt + 1) & 1]);
                asm volatile("cp.async.wait_group 0;\n" ::: "memory");
            }
            __syncthreads();
        }
        return;
    }

    // ===================== CONSUMER PATH (warps 0-3) =======================
    const int wn = wid;            // 64-col slab

    float d[4][8][4];
#pragma unroll
    for (int mi = 0; mi < 4; mi++)
#pragma unroll
        for (int ni = 0; ni < 8; ni++)
#pragma unroll
            for (int q = 0; q < 4; q++) d[mi][ni][q] = 0.0f;

    // ldmatrix lane addressing (halves)
    const int a_row = (lid & 15);
    const int a_col = (lid >> 4) * 8;
    const int b_row = wn * 64 + (lid & 7) + (lid >> 4) * 8;
    const int b_col = ((lid >> 3) & 1) * 8;

    __syncthreads();   // A(0), B(0) ready

    for (int kt = 0; kt < KT; kt++) {
        uint32_t sa = sA0 + (kt & 1) * A_STAGE_BYTES;
        uint32_t sbm = sB0 + (kt & 1) * B_STAGE_BYTES;

#pragma unroll
        for (int ks = 0; ks < 4; ks++) {
            uint32_t a[4][4];
            uint32_t b[8][2];
#pragma unroll
            for (int mi = 0; mi < 4; mi++) {
                uint32_t addr = sa + (uint32_t)((a_row + mi * 16) * LDS + ks * 16 + a_col) * 2;
                ldmatrix_x4(a[mi], addr);
            }
#pragma unroll
            for (int p = 0; p < 4; p++) {
                uint32_t t[4];
                uint32_t addr = sbm + (uint32_t)((b_row + p * 16) * LDS + ks * 16 + b_col) * 2;
                ldmatrix_x4(t, addr);
                b[2 * p][0] = t[0]; b[2 * p][1] = t[1];
                b[2 * p + 1][0] = t[2]; b[2 * p + 1][1] = t[3];
            }
#pragma unroll
            for (int mi = 0; mi < 4; mi++)
#pragma unroll
                for (int ni = 0; ni < 8; ni++)
                    mma_16816(d[mi][ni], a[mi], b[ni]);
        }
        __syncthreads();
    }

    // Epilogue: direct fp32 stores.
    const int er = m0 + (lid >> 2);
    const int ec = n0 + wn * 64 + (lid & 3) * 2;
#pragma unroll
    for (int mi = 0; mi < 4; mi++) {
#pragma unroll
        for (int ni = 0; ni < 8; ni++) {
            int r = er + mi * 16;
            int c = ec + ni * 8;
            float2 v0 = make_float2(d[mi][ni][0], d[mi][ni][1]);
            float2 v1 = make_float2(d[mi][ni][2], d[mi][ni][3]);
            *reinterpret_cast<float2*>(out + (size_t)r * GN + c) = v0;
            *reinterpret_cast<float2*>(out + (size_t)(r + 8) * GN + c) = v1;
        }
    }
}

// ---------------------------------------------------------------------------
// Launch
// ---------------------------------------------------------------------------
extern "C" void kernel_launch(void* const* d_in, const int* in_sizes, int n_in,
                              void* d_out, int out_size) {
    const float* x       = (const float*)d_in[0];   // (8192, 512)
    const float* coeffs  = (const float*)d_in[1];   // (512, 512, 8)
    const float* centers = (const float*)d_in[2];   // (512, 8)
    const float* slopes  = (const float*)d_in[3];   // (512, 8)
    float* out = (float*)d_out;                     // (8192, 512)

    // Pass 1: coeffs fp32 -> fp16
    coef_convert_kernel<<<(GN * GK / 4) / 256, 256>>>(coeffs);

    // Pass 2: warp-specialized fused basis + HMMA GEMM, 2 CTAs/SM
    cudaFuncSetAttribute(gemm_kernel, cudaFuncAttributeMaxDynamicSharedMemorySize,
                         SMEM_BYTES);
    dim3 grid(GN / BN, GM / BM);   // (2, 128) = 256 CTAs
    gemm_kernel<<<grid, THREADS, SMEM_BYTES>>>(x, centers, slopes, out);
}